// round 1
// baseline (speedup 1.0000x reference)
#include <cuda_runtime.h>
#include <cstdint>
#include <math_constants.h>

namespace {

constexpr int B_  = 32768;
constexpr int A_  = 32;
constexpr int D_  = 64;
constexpr int H_  = 128;
constexpr int K_  = 128;   // 2*D context width
constexpr int TB  = 64;    // batch rows per block
constexpr int NT  = 256;   // threads per block
constexpr int WS  = 132;   // padded stride for transposed weight tiles

struct Smem {
  float ctx [TB][K_];   // [b][k] context
  float hctx[TB][H_];   // [b][h] ctx@Wc^T + br1
  float hid [TB][H_];   // [b][h] hidden for current action
  float wbuf[K_][WS];   // transposed weight: [k][m] (W1[a]^T / Wc^T / W2[a]^T)
  float wp  [D_][WS];   // [d][h] Wp^T
  float preds[TB][D_];  // [b][d] preds for current action
  float wr2 [H_];
  float bestr[TB];
  int   flags[TB];
};

// Transpose-load src[rows][cols] (row stride src_stride) into dst[c][r].
__device__ __forceinline__ void load_wT(float (*dst)[WS], const float* __restrict__ src,
                                        int rows, int cols, int src_stride, int tid) {
  int total4 = rows * cols / 4;
  for (int idx = tid; idx < total4; idx += NT) {
    int flat = idx * 4;
    int r = flat / cols;
    int c = flat - r * cols;
    float4 v = *reinterpret_cast<const float4*>(src + r * src_stride + c);
    dst[c + 0][r] = v.x;
    dst[c + 1][r] = v.y;
    dst[c + 2][r] = v.z;
    dst[c + 3][r] = v.w;
  }
}

// acc[4][8] += X[b0..b0+3][:] * W[:][m0..m0+7]   (X is [b][K] stride XS)
template <int K, int XS>
__device__ __forceinline__ void mm48(const float* __restrict__ X, const float (*W)[WS],
                                     int b0, int m0, float acc[4][8]) {
#pragma unroll
  for (int j = 0; j < 4; j++)
#pragma unroll
    for (int m = 0; m < 8; m++) acc[j][m] = 0.f;

#pragma unroll 4
  for (int k = 0; k < K; k++) {
    float x0 = X[(b0 + 0) * XS + k];
    float x1 = X[(b0 + 1) * XS + k];
    float x2 = X[(b0 + 2) * XS + k];
    float x3 = X[(b0 + 3) * XS + k];
    float4 wa = *reinterpret_cast<const float4*>(&W[k][m0]);
    float4 wb = *reinterpret_cast<const float4*>(&W[k][m0 + 4]);
    float w[8] = {wa.x, wa.y, wa.z, wa.w, wb.x, wb.y, wb.z, wb.w};
#pragma unroll
    for (int m = 0; m < 8; m++) {
      acc[0][m] = fmaf(x0, w[m], acc[0][m]);
      acc[1][m] = fmaf(x1, w[m], acc[1][m]);
      acc[2][m] = fmaf(x2, w[m], acc[2][m]);
      acc[3][m] = fmaf(x3, w[m], acc[3][m]);
    }
  }
}

// acc[4][4] += X[b0..b0+3][:] * W[:][m0..m0+3]
template <int K, int XS>
__device__ __forceinline__ void mm44(const float* __restrict__ X, const float (*W)[WS],
                                     int b0, int m0, float acc[4][4]) {
#pragma unroll
  for (int j = 0; j < 4; j++)
#pragma unroll
    for (int m = 0; m < 4; m++) acc[j][m] = 0.f;

#pragma unroll 4
  for (int k = 0; k < K; k++) {
    float x0 = X[(b0 + 0) * XS + k];
    float x1 = X[(b0 + 1) * XS + k];
    float x2 = X[(b0 + 2) * XS + k];
    float x3 = X[(b0 + 3) * XS + k];
    float4 wa = *reinterpret_cast<const float4*>(&W[k][m0]);
    float w[4] = {wa.x, wa.y, wa.z, wa.w};
#pragma unroll
    for (int m = 0; m < 4; m++) {
      acc[0][m] = fmaf(x0, w[m], acc[0][m]);
      acc[1][m] = fmaf(x1, w[m], acc[1][m]);
      acc[2][m] = fmaf(x2, w[m], acc[2][m]);
      acc[3][m] = fmaf(x3, w[m], acc[3][m]);
    }
  }
}

}  // namespace

extern "C" __global__ void __launch_bounds__(NT, 1)
cmb_fused_kernel(const int* __restrict__ x, const int* __restrict__ y,
                 const float* __restrict__ cemb, const float* __restrict__ wemb,
                 const float* __restrict__ W1, const float* __restrict__ b1,
                 const float* __restrict__ W2, const float* __restrict__ b2,
                 const float* __restrict__ Wr1, const float* __restrict__ br1,
                 const float* __restrict__ Wr2, const float* __restrict__ br2,
                 float* __restrict__ out) {
  extern __shared__ char smraw[];
  Smem& sm = *reinterpret_cast<Smem*>(smraw);
  const int tid = threadIdx.x;
  const int b0g = blockIdx.x * TB;
  (void)br2;  // constant offset — irrelevant for argmin

  // ---- Phase 0: gather ctx rows, copy wemb rows, init small arrays ----
  {
    int b = tid >> 2;          // 0..63
    int part = tid & 3;        // 4 threads per batch row
    int gb = b0g + b;
    int x0 = x[gb * 2 + 0];
    int x1 = x[gb * 2 + 1];
#pragma unroll
    for (int q = 0; q < 8; q++) {
      int k = part * 32 + q * 4;
      const float* src = (k < 64) ? (cemb + (size_t)x0 * 64 + k)
                                  : (cemb + (size_t)x1 * 64 + (k - 64));
      *reinterpret_cast<float4*>(&sm.ctx[b][k]) =
          *reinterpret_cast<const float4*>(src);
    }
    int yy = y[gb];
#pragma unroll
    for (int q = 0; q < 4; q++) {
      int d = part * 16 + q * 4;
      *reinterpret_cast<float4*>(&out[(size_t)B_ * 64 + (size_t)gb * 64 + d]) =
          *reinterpret_cast<const float4*>(wemb + (size_t)yy * 64 + d);
    }
  }
  if (tid < TB) sm.bestr[tid] = CUDART_INF_F;
  if (tid < H_) sm.wr2[tid] = Wr2[tid];

  // Wc^T into wbuf (Wr1[:, :128], row stride 192), Wp^T into wp
  load_wT(sm.wbuf, Wr1, H_, K_, 192, tid);
  load_wT(sm.wp, Wr1 + 128, H_, D_, 192, tid);
  __syncthreads();

  const int btile = tid >> 4;        // 0..15, 4 batch rows each
  const int mtile = tid & 15;        // 0..15
  const int bb = btile * 4;

  // ---- Phase 1: hctx = ctx @ Wc^T + br1 ----
  {
    int m0 = mtile * 8;
    float acc[4][8];
    mm48<K_, K_>(&sm.ctx[0][0], sm.wbuf, bb, m0, acc);
#pragma unroll
    for (int j = 0; j < 4; j++)
#pragma unroll
      for (int m = 0; m < 8; m++)
        sm.hctx[bb + j][m0 + m] = acc[j][m] + br1[m0 + m];
  }
  __syncthreads();

  // ---- Action loop ----
  for (int a = 0; a < A_; a++) {
    // W1[a]^T into wbuf
    load_wT(sm.wbuf, W1 + (size_t)a * H_ * K_, H_, K_, K_, tid);
    __syncthreads();

    // hidden = ctx @ W1[a]^T + b1[a]
    {
      int m0 = mtile * 8;
      float acc[4][8];
      mm48<K_, K_>(&sm.ctx[0][0], sm.wbuf, bb, m0, acc);
#pragma unroll
      for (int j = 0; j < 4; j++)
#pragma unroll
        for (int m = 0; m < 8; m++)
          sm.hid[bb + j][m0 + m] = acc[j][m] + b1[a * H_ + m0 + m];
    }
    __syncthreads();

    // W2[a]^T into wbuf (W2[a] is [d][h])
    load_wT(sm.wbuf, W2 + (size_t)a * D_ * H_, D_, H_, H_, tid);
    __syncthreads();

    // preds = hidden @ W2[a]^T + b2[a]
    {
      int d0 = mtile * 4;
      float acc[4][4];
      mm44<H_, H_>(&sm.hid[0][0], sm.wbuf, bb, d0, acc);
#pragma unroll
      for (int j = 0; j < 4; j++)
#pragma unroll
        for (int m = 0; m < 4; m++)
          sm.preds[bb + j][d0 + m] = acc[j][m] + b2[a * D_ + d0 + m];
    }
    __syncthreads();

    // reward = sum_h relu(hctx + preds @ Wp^T) * Wr2
    {
      int m0 = mtile * 8;
      float acc[4][8];
      mm48<D_, D_>(&sm.preds[0][0], sm.wp, bb, m0, acc);
      float part[4];
#pragma unroll
      for (int j = 0; j < 4; j++) {
        float s = 0.f;
#pragma unroll
        for (int m = 0; m < 8; m++) {
          float h2 = acc[j][m] + sm.hctx[bb + j][m0 + m];
          h2 = fmaxf(h2, 0.f);
          s = fmaf(h2, sm.wr2[m0 + m], s);
        }
        part[j] = s;
      }
      // reduce over the 16 threads sharing this btile (lane groups of 16)
#pragma unroll
      for (int off = 8; off >= 1; off >>= 1)
#pragma unroll
        for (int j = 0; j < 4; j++)
          part[j] += __shfl_xor_sync(0xffffffffu, part[j], off);
      if (mtile == 0) {
#pragma unroll
        for (int j = 0; j < 4; j++) {
          int b = bb + j;
          if (part[j] < sm.bestr[b]) {  // strict < => first-min wins (matches argmin)
            sm.bestr[b] = part[j];
            sm.flags[b] = 1;
          } else {
            sm.flags[b] = 0;
          }
        }
      }
    }
    __syncthreads();

    // copy-on-improve: winning preds row -> out
    {
      int b = tid >> 2;
      int part_ = tid & 3;
      if (sm.flags[b]) {
        int gb = b0g + b;
#pragma unroll
        for (int q = 0; q < 4; q++) {
          int d = part_ * 16 + q * 4;
          *reinterpret_cast<float4*>(&out[(size_t)gb * 64 + d]) =
              *reinterpret_cast<const float4*>(&sm.preds[b][d]);
        }
      }
    }
    __syncthreads();
  }
}

extern "C" void kernel_launch(void* const* d_in, const int* in_sizes, int n_in,
                              void* d_out, int out_size) {
  (void)in_sizes; (void)n_in; (void)out_size;
  const int*   x    = (const int*)d_in[0];
  const int*   y    = (const int*)d_in[1];
  const float* cemb = (const float*)d_in[2];
  const float* wemb = (const float*)d_in[3];
  const float* W1   = (const float*)d_in[4];
  const float* b1   = (const float*)d_in[5];
  const float* W2   = (const float*)d_in[6];
  const float* b2   = (const float*)d_in[7];
  const float* Wr1  = (const float*)d_in[8];
  const float* br1  = (const float*)d_in[9];
  const float* Wr2  = (const float*)d_in[10];
  const float* br2  = (const float*)d_in[11];
  float* out = (float*)d_out;

  static_assert(sizeof(Smem) <= 227 * 1024, "smem budget");
  cudaFuncSetAttribute(cmb_fused_kernel,
                       cudaFuncAttributeMaxDynamicSharedMemorySize,
                       (int)sizeof(Smem));
  cmb_fused_kernel<<<B_ / TB, NT, sizeof(Smem)>>>(
      x, y, cemb, wemb, W1, b1, W2, b2, Wr1, br1, Wr2, br2, out);
}